// round 15
// baseline (speedup 1.0000x reference)
#include <cuda_runtime.h>
#include <math.h>

#define NB   32      // batch
#define PP   196     // pixels
#define ENC  2048
#define DECD 512
#define ATT  512
#define EMB  256
#define NV   30000
#define LL   21
#define NT   20      // decode steps
#define XK   (EMB + ENC)   // 2304

typedef unsigned long long u64;

// ---------- packed f32x2 helpers (sm_103a) ----------
__device__ __forceinline__ u64 pack2(float lo, float hi) {
    u64 r; asm("mov.b64 %0, {%1, %2};" : "=l"(r) : "f"(lo), "f"(hi)); return r;
}
__device__ __forceinline__ void unpack2(u64 v, float& lo, float& hi) {
    asm("mov.b64 {%0, %1}, %2;" : "=f"(lo), "=f"(hi) : "l"(v));
}
__device__ __forceinline__ u64 ffma2(u64 a, u64 b, u64 c) {
    u64 d; asm("fma.rn.f32x2 %0, %1, %2, %3;" : "=l"(d) : "l"(a), "l"(b), "l"(c)); return d;
}
__device__ __forceinline__ u64 fadd2(u64 a, u64 b) {
    u64 d; asm("add.rn.f32x2 %0, %1, %2;" : "=l"(d) : "l"(a), "l"(b)); return d;
}
__device__ __forceinline__ unsigned to_tf32(float f) {
    unsigned r; asm("cvt.rna.tf32.f32 %0, %1;" : "=r"(r) : "f"(f)); return r;
}

// ---------- persistent scratch (no cudaMalloc allowed) ----------
__device__ __align__(16) float g_att1 [NB * PP * ATT];     // 12.8 MB
__device__ __align__(16) float g_mean [NB * ENC];
__device__ __align__(16) float g_h    [NB * DECD];         // h0
__device__ __align__(16) float g_c    [NB * DECD];
__device__ __align__(16) float g_alpha[NB * PP];
__device__ __align__(16) float g_x    [NB * XK];
__device__ __align__(16) float g_hall [NT * NB * DECD];    // h_t, rows m = t*32+b

// ============================================================
// mean over P
// ============================================================
__global__ void mean_kernel(const float* __restrict__ enc, float* __restrict__ mean)
{
    int b = blockIdx.x;
    for (int k = threadIdx.x; k < ENC; k += 256) {
        const float* p0 = enc + (size_t)b * PP * ENC + k;
        float s = 0.f;
        #pragma unroll 4
        for (int p = 0; p < PP; p++) s += p0[(size_t)p * ENC];
        mean[b * ENC + k] = s * (1.0f / PP);
    }
}

// ============================================================
// TC GEMM v2 (R10-proven, UNCHANGED): 128x128 tile, BK=32, cp.async
// double-buffered, conflict-free [row][36] smem, tf32 m16n8k8.
// ============================================================
#define TLE  36
#define SBUF (128 * TLE)

__global__ __launch_bounds__(256, 2) void gemm_tc2_kernel(
    const float* __restrict__ A, const float* __restrict__ W,
    const float* __restrict__ bias, float* __restrict__ C,
    int K, int Ntot, int ldc, int remap)
{
    extern __shared__ __align__(16) unsigned smem_dyn[];
    unsigned sbase;
    asm("{ .reg .u64 t; cvta.to.shared.u64 t, %1; cvt.u32.u64 %0, t; }"
        : "=r"(sbase) : "l"(smem_dyn));

    const int tid  = threadIdx.x;
    const int m0   = blockIdx.y * 128;
    const int n0   = blockIdx.x * 128;
    const int lane = tid & 31;
    const int warp = tid >> 5;
    const int wm   = warp >> 2;
    const int wn   = warp & 3;
    const int g    = lane >> 2;
    const int tig  = lane & 3;

    float acc[4][4][4];
    #pragma unroll
    for (int i = 0; i < 4; i++)
        #pragma unroll
        for (int j = 0; j < 4; j++)
            #pragma unroll
            for (int q = 0; q < 4; q++) acc[i][j][q] = 0.f;

    const int KT = K >> 5;

    int srow[4], scol[4];
    #pragma unroll
    for (int r = 0; r < 4; r++) {
        int f = tid + r * 256;
        srow[r] = f >> 3;
        scol[r] = f & 7;
    }

    auto issue = [&](int kt, int s) {
        const int kbase = kt * 32;
        const unsigned aB = sbase + (unsigned)((s ? 2 * SBUF : 0) * 4);
        const unsigned bB = sbase + (unsigned)(((s ? 3 : 1) * SBUF) * 4);
        #pragma unroll
        for (int r = 0; r < 4; r++) {
            const float* src = A + (size_t)(m0 + srow[r]) * K + kbase + scol[r] * 4;
            unsigned dst = aB + (unsigned)((srow[r] * TLE + scol[r] * 4) * 4);
            asm volatile("cp.async.cg.shared.global [%0], [%1], 16;"
                         :: "r"(dst), "l"(src));
        }
        #pragma unroll
        for (int r = 0; r < 4; r++) {
            int n = n0 + srow[r];
            if (n >= Ntot) n = Ntot - 1;
            const float* src = W + (size_t)n * K + kbase + scol[r] * 4;
            unsigned dst = bB + (unsigned)((srow[r] * TLE + scol[r] * 4) * 4);
            asm volatile("cp.async.cg.shared.global [%0], [%1], 16;"
                         :: "r"(dst), "l"(src));
        }
        asm volatile("cp.async.commit_group;");
    };

    issue(0, 0);

    #pragma unroll 1
    for (int kt = 0; kt < KT; kt++) {
        if (kt + 1 < KT) issue(kt + 1, (kt + 1) & 1);
        else             asm volatile("cp.async.commit_group;");
        asm volatile("cp.async.wait_group 1;");
        __syncthreads();

        const unsigned* as = smem_dyn + ((kt & 1) ? 2 * SBUF : 0);
        const unsigned* bs = smem_dyn + ((kt & 1) ? 3 : 1) * SBUF;

        #pragma unroll
        for (int kc = 0; kc < 4; kc++) {
            const int kb = kc * 8;
            unsigned bF[4][2];
            #pragma unroll
            for (int j = 0; j < 4; j++) {
                int nl = wn * 32 + j * 8 + g;
                bF[j][0] = to_tf32(__uint_as_float(bs[nl * TLE + kb + tig]));
                bF[j][1] = to_tf32(__uint_as_float(bs[nl * TLE + kb + tig + 4]));
            }
            #pragma unroll
            for (int i = 0; i < 4; i++) {
                int ml = wm * 64 + i * 16 + g;
                unsigned a0 = to_tf32(__uint_as_float(as[ml * TLE + kb + tig]));
                unsigned a1 = to_tf32(__uint_as_float(as[(ml + 8) * TLE + kb + tig]));
                unsigned a2 = to_tf32(__uint_as_float(as[ml * TLE + kb + tig + 4]));
                unsigned a3 = to_tf32(__uint_as_float(as[(ml + 8) * TLE + kb + tig + 4]));
                #pragma unroll
                for (int j = 0; j < 4; j++) {
                    asm volatile(
                        "mma.sync.aligned.m16n8k8.row.col.f32.tf32.tf32.f32 "
                        "{%0,%1,%2,%3}, {%4,%5,%6,%7}, {%8,%9}, {%0,%1,%2,%3};"
                        : "+f"(acc[i][j][0]), "+f"(acc[i][j][1]),
                          "+f"(acc[i][j][2]), "+f"(acc[i][j][3])
                        : "r"(a0), "r"(a1), "r"(a2), "r"(a3),
                          "r"(bF[j][0]), "r"(bF[j][1]));
                }
            }
        }
        __syncthreads();
    }

    #pragma unroll
    for (int i = 0; i < 4; i++) {
        int r0 = m0 + wm * 64 + i * 16 + g;
        #pragma unroll
        for (int j = 0; j < 4; j++) {
            int nb = n0 + wn * 32 + j * 8 + tig * 2;
            #pragma unroll
            for (int q = 0; q < 4; q++) {
                int m = r0 + (q >> 1) * 8;
                int n = nb + (q & 1);
                if (n >= Ntot) continue;
                float v = acc[i][j][q] + bias[n];
                if (remap) {
                    int tt = m >> 5, bb = m & 31;
                    C[(size_t)(bb * NT + tt) * Ntot + n] = v;
                } else {
                    C[(size_t)m * ldc + n] = v;
                }
            }
        }
    }
}

// ============================================================
// Pipelined skinny GEMM (init h0/c0 only; R9/R10-proven)
// ============================================================
__global__ __launch_bounds__(256) void skinny_pipe_kernel(
    const float* __restrict__ A1, const float* __restrict__ W1, int K1,
    const float* __restrict__ bias1, float* __restrict__ out, int ldc)
{
    __shared__ __align__(16) u64 xs[16][64];
    const int tid  = threadIdx.x;
    const int lane = tid & 31;
    const int w    = tid >> 5;
    const int ng   = w & 3;
    const int bg   = w >> 2;
    const int n0   = blockIdx.x * 16 + ng * 4;
    const int b2s  = tid >> 4;
    const int c4   = tid & 15;

    u64 acc[8][4];
    #pragma unroll
    for (int i = 0; i < 8; i++)
        #pragma unroll
        for (int j = 0; j < 4; j++) acc[i][j] = 0ull;

    float4 lo4 = *(const float4*)(A1 + (size_t)(2 * b2s)     * K1 + c4 * 4);
    float4 hi4 = *(const float4*)(A1 + (size_t)(2 * b2s + 1) * K1 + c4 * 4);
    float w0[4], w1[4];
    #pragma unroll
    for (int j = 0; j < 4; j++) {
        const float* r = W1 + (size_t)(n0 + j) * K1 + lane;
        w0[j] = r[0]; w1[j] = r[32];
    }

    #pragma unroll 1
    for (int k0 = 0; k0 < K1; k0 += 64) {
        __syncthreads();
        xs[b2s][c4*4+0] = pack2(lo4.x, hi4.x);
        xs[b2s][c4*4+1] = pack2(lo4.y, hi4.y);
        xs[b2s][c4*4+2] = pack2(lo4.z, hi4.z);
        xs[b2s][c4*4+3] = pack2(lo4.w, hi4.w);
        __syncthreads();
        u64 wd0[4], wd1[4];
        #pragma unroll
        for (int j = 0; j < 4; j++) {
            wd0[j] = pack2(w0[j], w0[j]);
            wd1[j] = pack2(w1[j], w1[j]);
        }
        if (k0 + 64 < K1) {
            lo4 = *(const float4*)(A1 + (size_t)(2 * b2s)     * K1 + k0 + 64 + c4 * 4);
            hi4 = *(const float4*)(A1 + (size_t)(2 * b2s + 1) * K1 + k0 + 64 + c4 * 4);
            #pragma unroll
            for (int j = 0; j < 4; j++) {
                const float* r = W1 + (size_t)(n0 + j) * K1 + k0 + 64 + lane;
                w0[j] = r[0]; w1[j] = r[32];
            }
        }
        #pragma unroll
        for (int i = 0; i < 8; i++) {
            u64 x0 = xs[bg * 8 + i][lane];
            u64 x1 = xs[bg * 8 + i][lane + 32];
            #pragma unroll
            for (int j = 0; j < 4; j++) {
                acc[i][j] = ffma2(x0, wd0[j], acc[i][j]);
                acc[i][j] = ffma2(x1, wd1[j], acc[i][j]);
            }
        }
    }
    #pragma unroll
    for (int i = 0; i < 8; i++)
        #pragma unroll
        for (int j = 0; j < 4; j++) {
            u64 v = acc[i][j];
            #pragma unroll
            for (int o = 16; o > 0; o >>= 1)
                v = fadd2(v, __shfl_xor_sync(0xffffffffu, v, o));
            acc[i][j] = v;
        }
    if (lane == 0) {
        #pragma unroll
        for (int i = 0; i < 8; i++) {
            int b = (bg * 8 + i) * 2;
            #pragma unroll
            for (int j = 0; j < 4; j++) {
                int n = n0 + j;
                float lo, hi; unpack2(acc[i][j], lo, hi);
                out[(size_t)b       * ldc + n] = lo + bias1[n];
                out[(size_t)(b + 1) * ldc + n] = hi + bias1[n];
            }
        }
    }
}

// ============================================================
// Fused attention, 512 threads: att2 (per-thread Wd row dot) + escore
// (16 warps, 2 p's per iter) + softmax + alpha writes + embedding gather.
// ============================================================
__global__ __launch_bounds__(512) void att_fused_kernel(
    const float* __restrict__ att1, const float* __restrict__ h_in,
    const float* __restrict__ Wd,   const float* __restrict__ bd,
    const float* __restrict__ Wf,   const float* __restrict__ bf,
    float* __restrict__ alpha, float* __restrict__ out_alpha, int t,
    const int* __restrict__ captions, const float* __restrict__ emb,
    float* __restrict__ xbuf)
{
    __shared__ __align__(16) float sH[DECD];
    __shared__ __align__(16) float sA[ATT];
    __shared__ __align__(16) float sW[ATT];
    __shared__ float sE[256];
    __shared__ float red[256];
    __shared__ int s_idx;

    const int b = blockIdx.x, tid = threadIdx.x;

    sH[tid] = h_in[(size_t)b * DECD + tid];     // 512 threads == DECD
    sW[tid] = Wf[tid];                           // 512 threads == ATT
    if (tid < 256) sE[tid] = -3.4e38f;
    __syncthreads();

    // att2[a] = bd[a] + Wd[a]·h  (one row per thread; Wd rows L2-resident)
    {
        const float4* wr = (const float4*)(Wd + (size_t)tid * DECD);
        const float4* hh = (const float4*)sH;
        float a0 = 0.f, a1 = 0.f;
        #pragma unroll 8
        for (int kk = 0; kk < DECD / 8; kk++) {
            float4 wv0 = wr[2 * kk],     hv0 = hh[2 * kk];
            float4 wv1 = wr[2 * kk + 1], hv1 = hh[2 * kk + 1];
            a0 += wv0.x * hv0.x + wv0.y * hv0.y + wv0.z * hv0.z + wv0.w * hv0.w;
            a1 += wv1.x * hv1.x + wv1.y * hv1.y + wv1.z * hv1.z + wv1.w * hv1.w;
        }
        sA[tid] = a0 + a1 + bd[tid];
    }
    __syncthreads();

    const int w = tid >> 5, lane = tid & 31;    // 16 warps
    for (int p = w; p < PP; p += 32) {
        const int p2 = p + 16;
        const bool has2 = (p2 < PP);
        const float4* row0 = (const float4*)(att1 + ((size_t)b * PP + p) * ATT);
        const float4* row1 = (const float4*)(att1 + ((size_t)b * PP + (has2 ? p2 : p)) * ATT);
        const float4* a4  = (const float4*)sA;
        const float4* w4  = (const float4*)sW;
        float acc0 = 0.f, acc1 = 0.f;
        #pragma unroll
        for (int c = lane; c < ATT / 4; c += 32) {
            float4 h = a4[c], f = w4[c];
            float4 v0 = row0[c], v1 = row1[c];
            acc0 += fmaxf(v0.x + h.x, 0.f) * f.x + fmaxf(v0.y + h.y, 0.f) * f.y
                  + fmaxf(v0.z + h.z, 0.f) * f.z + fmaxf(v0.w + h.w, 0.f) * f.w;
            acc1 += fmaxf(v1.x + h.x, 0.f) * f.x + fmaxf(v1.y + h.y, 0.f) * f.y
                  + fmaxf(v1.z + h.z, 0.f) * f.z + fmaxf(v1.w + h.w, 0.f) * f.w;
        }
        #pragma unroll
        for (int o = 16; o > 0; o >>= 1) {
            acc0 += __shfl_xor_sync(0xffffffffu, acc0, o);
            acc1 += __shfl_xor_sync(0xffffffffu, acc1, o);
        }
        if (lane == 0) {
            sE[p] = acc0 + bf[0];
            if (has2) sE[p2] = acc1 + bf[0];
        }
    }
    __syncthreads();

    // softmax over sE[0..195] using threads 0..255
    float v = (tid < 256) ? sE[tid] : -3.4e38f;
    if (tid < 256) red[tid] = v;
    __syncthreads();
    #pragma unroll
    for (int s = 128; s > 0; s >>= 1) {
        if (tid < s) red[tid] = fmaxf(red[tid], red[tid + s]);
        __syncthreads();
    }
    float mx = red[0]; __syncthreads();
    float ex = (tid < PP) ? expf(v - mx) : 0.f;
    if (tid < 256) red[tid] = ex;
    __syncthreads();
    #pragma unroll
    for (int s = 128; s > 0; s >>= 1) {
        if (tid < s) red[tid] += red[tid + s];
        __syncthreads();
    }
    float inv = 1.0f / red[0];
    if (tid < PP) {
        float a = ex * inv;
        alpha[b * PP + tid] = a;
        out_alpha[(size_t)(b * NT + t) * PP + tid] = a;
    }

    if (tid == 0) {
        // dtype hedge: int64 captions -> every odd 32-bit word is 0
        bool is64 = true;
        #pragma unroll
        for (int i = 0; i < 32; i++)
            if (captions[2 * i + 1] != 0) is64 = false;
        int pos = b * LL + t;
        s_idx = is64 ? captions[2 * pos] : captions[pos];
    }
    __syncthreads();
    if (tid < EMB)
        xbuf[(size_t)b * XK + tid] = emb[(size_t)s_idx * EMB + tid];
}

// ============================================================
// awe: float2 per thread, p-unroll 8 (MLP 8). grid (4, NB).
// awe[b][k] = sum_p alpha[b,p] * enc[b,p,k] -> x buffer at +EMB
// ============================================================
__global__ void awe_kernel(const float* __restrict__ enc,
                           const float* __restrict__ alpha,
                           float* __restrict__ xbuf)
{
    __shared__ float al[PP];
    const int b  = blockIdx.y;
    const int k0 = blockIdx.x * 512 + threadIdx.x * 2;
    if (threadIdx.x < PP) al[threadIdx.x] = alpha[b * PP + threadIdx.x];
    __syncthreads();
    const float2* ep = (const float2*)(enc + (size_t)b * PP * ENC) + (k0 >> 1);
    float ax = 0.f, ay = 0.f;
    #pragma unroll 8
    for (int p = 0; p < PP; p++) {
        float a = al[p];
        float2 v = ep[(size_t)p * (ENC / 2)];
        ax += a * v.x; ay += a * v.y;
    }
    xbuf[(size_t)b * XK + EMB + k0]     = ax;
    xbuf[(size_t)b * XK + EMB + k0 + 1] = ay;
}

// ============================================================
// Gates GEMM + fused LSTM (R10-proven), pipelined across Wih/Whh.
// ============================================================
#define NCH (XK / 64 + DECD / 64)   // 44 chunks
__global__ __launch_bounds__(256) void gates_lstm_kernel(
    const float* __restrict__ x,    const float* __restrict__ Wih,
    const float* __restrict__ h_in, const float* __restrict__ Whh,
    const float* __restrict__ bih,  const float* __restrict__ bhh,
    float* __restrict__ c, float* __restrict__ h_out)
{
    __shared__ __align__(16) u64 xs[16][64];
    const int tid  = threadIdx.x;
    const int lane = tid & 31;
    const int wrp  = tid >> 5;
    const int ng   = wrp & 3;
    const int bg   = wrp >> 2;
    const int jcol = blockIdx.x * 4 + ng;
    const int b2s  = tid >> 4;
    const int c4   = tid & 15;

    int nj[4];
    #pragma unroll
    for (int j = 0; j < 4; j++) nj[j] = j * DECD + jcol;

    u64 acc[8][4];
    #pragma unroll
    for (int i = 0; i < 8; i++)
        #pragma unroll
        for (int j = 0; j < 4; j++) acc[i][j] = 0ull;

    float4 lo4 = *(const float4*)(x + (size_t)(2 * b2s)     * XK + c4 * 4);
    float4 hi4 = *(const float4*)(x + (size_t)(2 * b2s + 1) * XK + c4 * 4);
    float w0[4], w1[4];
    #pragma unroll
    for (int j = 0; j < 4; j++) {
        const float* r = Wih + (size_t)nj[j] * XK + lane;
        w0[j] = r[0]; w1[j] = r[32];
    }

    #pragma unroll 1
    for (int cc = 0; cc < NCH; cc++) {
        __syncthreads();
        xs[b2s][c4*4+0] = pack2(lo4.x, hi4.x);
        xs[b2s][c4*4+1] = pack2(lo4.y, hi4.y);
        xs[b2s][c4*4+2] = pack2(lo4.z, hi4.z);
        xs[b2s][c4*4+3] = pack2(lo4.w, hi4.w);
        __syncthreads();
        u64 wd0[4], wd1[4];
        #pragma unroll
        for (int j = 0; j < 4; j++) {
            wd0[j] = pack2(w0[j], w0[j]);
            wd1[j] = pack2(w1[j], w1[j]);
        }
        if (cc + 1 < NCH) {
            int nc = cc + 1;
            const float* An; const float* Wn; int Kn, kn;
            if (nc < XK / 64) { An = x;    Wn = Wih; Kn = XK;   kn = nc * 64; }
            else              { An = h_in; Wn = Whh; Kn = DECD; kn = (nc - XK / 64) * 64; }
            lo4 = *(const float4*)(An + (size_t)(2 * b2s)     * Kn + kn + c4 * 4);
            hi4 = *(const float4*)(An + (size_t)(2 * b2s + 1) * Kn + kn + c4 * 4);
            #pragma unroll
            for (int j = 0; j < 4; j++) {
                const float* r = Wn + (size_t)nj[j] * Kn + kn + lane;
                w0[j] = r[0]; w1[j] = r[32];
            }
        }
        #pragma unroll
        for (int i = 0; i < 8; i++) {
            u64 x0 = xs[bg * 8 + i][lane];
            u64 x1 = xs[bg * 8 + i][lane + 32];
            #pragma unroll
            for (int j = 0; j < 4; j++) {
                acc[i][j] = ffma2(x0, wd0[j], acc[i][j]);
                acc[i][j] = ffma2(x1, wd1[j], acc[i][j]);
            }
        }
    }
    #pragma unroll
    for (int i = 0; i < 8; i++)
        #pragma unroll
        for (int j = 0; j < 4; j++) {
            u64 v = acc[i][j];
            #pragma unroll
            for (int o = 16; o > 0; o >>= 1)
                v = fadd2(v, __shfl_xor_sync(0xffffffffu, v, o));
            acc[i][j] = v;
        }
    if (lane == 0) {
        #pragma unroll
        for (int i = 0; i < 8; i++) {
            int b0 = (bg * 8 + i) * 2;
            float gv[4][2];
            #pragma unroll
            for (int j = 0; j < 4; j++) {
                float bb = bih[nj[j]] + bhh[nj[j]];
                float lo, hi; unpack2(acc[i][j], lo, hi);
                gv[j][0] = lo + bb; gv[j][1] = hi + bb;
            }
            #pragma unroll
            for (int hs = 0; hs < 2; hs++) {
                int bb = b0 + hs;
                float ig = gv[0][hs], fg = gv[1][hs];
                float gg = gv[2][hs], og = gv[3][hs];
                float si = 1.f / (1.f + expf(-ig));
                float sf = 1.f / (1.f + expf(-fg));
                float so = 1.f / (1.f + expf(-og));
                float co = c[(size_t)bb * DECD + jcol];
                float cn = sf * co + si * tanhf(gg);
                float hn = so * tanhf(cn);
                c[(size_t)bb * DECD + jcol]     = cn;
                h_out[(size_t)bb * DECD + jcol] = hn;
            }
        }
    }
}

// ============================================================
extern "C" void kernel_launch(void* const* d_in, const int* in_sizes, int n_in,
                              void* d_out, int out_size)
{
    const float* enc  = (const float*)d_in[0];
    const int*   caps = (const int*)  d_in[1];
    const float* emb  = (const float*)d_in[3];
    const float* We   = (const float*)d_in[4];
    const float* be   = (const float*)d_in[5];
    const float* Wd   = (const float*)d_in[6];
    const float* bd   = (const float*)d_in[7];
    const float* Wf   = (const float*)d_in[8];
    const float* bf   = (const float*)d_in[9];
    const float* Wih  = (const float*)d_in[10];
    const float* bih  = (const float*)d_in[11];
    const float* Whh  = (const float*)d_in[12];
    const float* bhh  = (const float*)d_in[13];
    const float* Wfc  = (const float*)d_in[14];
    const float* bfc  = (const float*)d_in[15];
    const float* Wh0  = (const float*)d_in[16];
    const float* bh0  = (const float*)d_in[17];
    const float* Wc0  = (const float*)d_in[18];
    const float* bc0  = (const float*)d_in[19];

    float* out       = (float*)d_out;                  // predictions [32,20,30000]
    float* out_alpha = out + (size_t)NB * NT * NV;     // alphas      [32,20,196]

    float *p_att1, *p_mean, *p_h, *p_c, *p_alpha, *p_x, *p_hall;
    cudaGetSymbolAddress((void**)&p_att1,  g_att1);
    cudaGetSymbolAddress((void**)&p_mean,  g_mean);
    cudaGetSymbolAddress((void**)&p_h,     g_h);
    cudaGetSymbolAddress((void**)&p_c,     g_c);
    cudaGetSymbolAddress((void**)&p_alpha, g_alpha);
    cudaGetSymbolAddress((void**)&p_x,     g_x);
    cudaGetSymbolAddress((void**)&p_hall,  g_hall);

    const int dyn_smem = 4 * SBUF * 4;   // 73,728 bytes
    cudaFuncSetAttribute(gemm_tc2_kernel,
                         cudaFuncAttributeMaxDynamicSharedMemorySize, dyn_smem);

    // ---- init ----
    mean_kernel<<<NB, 256>>>(enc, p_mean);
    skinny_pipe_kernel<<<DECD / 16, 256>>>(p_mean, Wh0, ENC, bh0, p_h, DECD);
    skinny_pipe_kernel<<<DECD / 16, 256>>>(p_mean, Wc0, ENC, bc0, p_c, DECD);
    gemm_tc2_kernel<<<dim3(ATT / 128, (NB * PP) / 128), 256, dyn_smem>>>(
        enc, We, be, p_att1, ENC, ATT, ATT, 0);

    // ---- decode loop: 3 launches/step (att2 merged into att_fused) ----
    for (int t = 0; t < NT; t++) {
        const float* h_in  = (t == 0) ? p_h : (p_hall + (size_t)(t - 1) * NB * DECD);
        float*       h_out = p_hall + (size_t)t * NB * DECD;
        att_fused_kernel<<<NB, 512>>>(p_att1, h_in, Wd, bd, Wf, bf, p_alpha,
                                      out_alpha, t, caps, emb, p_x);
        awe_kernel<<<dim3(4, NB), 256>>>(enc, p_alpha, p_x);
        gates_lstm_kernel<<<DECD / 4, 256>>>(p_x, Wih, h_in, Whh,
                                             bih, bhh, p_c, h_out);
    }

    // ---- batched predictions: [640,512] @ [512,30000]^T, rows remapped ----
    gemm_tc2_kernel<<<dim3((NV + 127) / 128, (NT * NB) / 128), 256, dyn_smem>>>(
        p_hall, Wfc, bfc, out, DECD, NV, 0, 1);
}

// round 16
// speedup vs baseline: 1.2877x; 1.2877x over previous
#include <cuda_runtime.h>
#include <math.h>

#define NB   32      // batch
#define PP   196     // pixels
#define ENC  2048
#define DECD 512
#define ATT  512
#define EMB  256
#define NV   30000
#define LL   21
#define NT   20      // decode steps
#define XK   (EMB + ENC)   // 2304

typedef unsigned long long u64;

// ---------- packed f32x2 helpers (sm_103a) ----------
__device__ __forceinline__ u64 pack2(float lo, float hi) {
    u64 r; asm("mov.b64 %0, {%1, %2};" : "=l"(r) : "f"(lo), "f"(hi)); return r;
}
__device__ __forceinline__ void unpack2(u64 v, float& lo, float& hi) {
    asm("mov.b64 {%0, %1}, %2;" : "=f"(lo), "=f"(hi) : "l"(v));
}
__device__ __forceinline__ u64 ffma2(u64 a, u64 b, u64 c) {
    u64 d; asm("fma.rn.f32x2 %0, %1, %2, %3;" : "=l"(d) : "l"(a), "l"(b), "l"(c)); return d;
}
__device__ __forceinline__ u64 fadd2(u64 a, u64 b) {
    u64 d; asm("add.rn.f32x2 %0, %1, %2;" : "=l"(d) : "l"(a), "l"(b)); return d;
}

// ---------- persistent scratch (no cudaMalloc allowed) ----------
__device__ __align__(16) float g_att1 [NB * PP * ATT];     // 12.8 MB
__device__ __align__(16) float g_mean [NB * ENC];
__device__ __align__(16) float g_h    [NB * DECD];         // h0
__device__ __align__(16) float g_c    [NB * DECD];
__device__ __align__(16) float g_att2 [NB * ATT];
__device__ __align__(16) float g_alpha[NB * PP];
__device__ __align__(16) float g_x    [NB * XK];
__device__ __align__(16) float g_hall [NT * NB * DECD];    // h_t, rows m = t*32+b

// ============================================================
// mean over P
// ============================================================
__global__ void mean_kernel(const float* __restrict__ enc, float* __restrict__ mean)
{
    int b = blockIdx.x;
    for (int k = threadIdx.x; k < ENC; k += 256) {
        const float* p0 = enc + (size_t)b * PP * ENC + k;
        float s = 0.f;
        #pragma unroll 4
        for (int p = 0; p < PP; p++) s += p0[(size_t)p * ENC];
        mean[b * ENC + k] = s * (1.0f / PP);
    }
}

// ============================================================
// TC GEMM v3: 128x128 tile, BK=32, 3-stage cp.async pipeline,
// ONE __syncthreads per k-tile, raw-fp32-as-tf32 operands (no cvt).
// C[M,Ntot] = A[M,K] @ W[Ntot,K]^T + bias.
// M % 128 == 0, K % 32 == 0, N edge clamped/guarded.
// remap=1 (preds): row m=t*32+b -> C[(b*NT+t)*Ntot+n].
// Dynamic smem: 3 stages * 2 * 128*36 * 4 = 110,592 bytes.
// ============================================================
#define TLE  36
#define SBUF (128 * TLE)

__global__ __launch_bounds__(256) void gemm_tc3_kernel(
    const float* __restrict__ A, const float* __restrict__ W,
    const float* __restrict__ bias, float* __restrict__ C,
    int K, int Ntot, int ldc, int remap)
{
    extern __shared__ __align__(16) unsigned smem_dyn[];
    unsigned sbase;
    asm("{ .reg .u64 t; cvta.to.shared.u64 t, %1; cvt.u32.u64 %0, t; }"
        : "=r"(sbase) : "l"(smem_dyn));

    const int tid  = threadIdx.x;
    const int m0   = blockIdx.y * 128;
    const int n0   = blockIdx.x * 128;
    const int lane = tid & 31;
    const int warp = tid >> 5;
    const int wm   = warp >> 2;
    const int wn   = warp & 3;
    const int g    = lane >> 2;
    const int tig  = lane & 3;

    float acc[4][4][4];
    #pragma unroll
    for (int i = 0; i < 4; i++)
        #pragma unroll
        for (int j = 0; j < 4; j++)
            #pragma unroll
            for (int q = 0; q < 4; q++) acc[i][j][q] = 0.f;

    const int KT = K >> 5;

    int srow[4], scol[4];
    #pragma unroll
    for (int r = 0; r < 4; r++) {
        int f = tid + r * 256;
        srow[r] = f >> 3;
        scol[r] = f & 7;
    }

    // issue one k-tile into stage kt%3
    auto issue = [&](int kt) {
        const int s = kt % 3;
        const int kbase = kt * 32;
        const unsigned aB = sbase + (unsigned)(s * 2 * SBUF * 4);
        const unsigned bB = aB + (unsigned)(SBUF * 4);
        #pragma unroll
        for (int r = 0; r < 4; r++) {
            const float* src = A + (size_t)(m0 + srow[r]) * K + kbase + scol[r] * 4;
            unsigned dst = aB + (unsigned)((srow[r] * TLE + scol[r] * 4) * 4);
            asm volatile("cp.async.cg.shared.global [%0], [%1], 16;"
                         :: "r"(dst), "l"(src));
        }
        #pragma unroll
        for (int r = 0; r < 4; r++) {
            int n = n0 + srow[r];
            if (n >= Ntot) n = Ntot - 1;
            const float* src = W + (size_t)n * K + kbase + scol[r] * 4;
            unsigned dst = bB + (unsigned)((srow[r] * TLE + scol[r] * 4) * 4);
            asm volatile("cp.async.cg.shared.global [%0], [%1], 16;"
                         :: "r"(dst), "l"(src));
        }
        asm volatile("cp.async.commit_group;");
    };

    issue(0);
    issue(1);

    #pragma unroll 1
    for (int kt = 0; kt < KT; kt++) {
        // group kt must be complete before computing it; allow the 1 newest pending
        asm volatile("cp.async.wait_group 1;");
        __syncthreads();     // makes stage kt%3 visible to all; frees stage (kt-1)%3
        if (kt + 2 < KT) issue(kt + 2);       // writes stage (kt-1)%3 — safe post-sync
        else asm volatile("cp.async.commit_group;");   // keep wait counter exact

        const unsigned* as = smem_dyn + (kt % 3) * 2 * SBUF;
        const unsigned* bs = as + SBUF;

        #pragma unroll
        for (int kc = 0; kc < 4; kc++) {
            const int kb = kc * 8;
            unsigned bF[4][2];
            #pragma unroll
            for (int j = 0; j < 4; j++) {
                int nl = wn * 32 + j * 8 + g;
                bF[j][0] = bs[nl * TLE + kb + tig];        // raw fp32 bits as tf32
                bF[j][1] = bs[nl * TLE + kb + tig + 4];
            }
            #pragma unroll
            for (int i = 0; i < 4; i++) {
                int ml = wm * 64 + i * 16 + g;
                unsigned a0 = as[ml * TLE + kb + tig];
                unsigned a1 = as[(ml + 8) * TLE + kb + tig];
                unsigned a2 = as[ml * TLE + kb + tig + 4];
                unsigned a3 = as[(ml + 8) * TLE + kb + tig + 4];
                #pragma unroll
                for (int j = 0; j < 4; j++) {
                    asm volatile(
                        "mma.sync.aligned.m16n8k8.row.col.f32.tf32.tf32.f32 "
                        "{%0,%1,%2,%3}, {%4,%5,%6,%7}, {%8,%9}, {%0,%1,%2,%3};"
                        : "+f"(acc[i][j][0]), "+f"(acc[i][j][1]),
                          "+f"(acc[i][j][2]), "+f"(acc[i][j][3])
                        : "r"(a0), "r"(a1), "r"(a2), "r"(a3),
                          "r"(bF[j][0]), "r"(bF[j][1]));
                }
            }
        }
    }

    #pragma unroll
    for (int i = 0; i < 4; i++) {
        int r0 = m0 + wm * 64 + i * 16 + g;
        #pragma unroll
        for (int j = 0; j < 4; j++) {
            int nb = n0 + wn * 32 + j * 8 + tig * 2;
            #pragma unroll
            for (int q = 0; q < 4; q++) {
                int m = r0 + (q >> 1) * 8;
                int n = nb + (q & 1);
                if (n >= Ntot) continue;
                float v = acc[i][j][q] + bias[n];
                if (remap) {
                    int tt = m >> 5, bb = m & 31;
                    C[(size_t)(bb * NT + tt) * Ntot + n] = v;
                } else {
                    C[(size_t)m * ldc + n] = v;
                }
            }
        }
    }
}

// ============================================================
// Pipelined skinny GEMM (R9/R10-proven): out[b][n] = b1[n] + A1[b]·W1[n]
// ============================================================
__global__ __launch_bounds__(256) void skinny_pipe_kernel(
    const float* __restrict__ A1, const float* __restrict__ W1, int K1,
    const float* __restrict__ bias1, float* __restrict__ out, int ldc)
{
    __shared__ __align__(16) u64 xs[16][64];
    const int tid  = threadIdx.x;
    const int lane = tid & 31;
    const int w    = tid >> 5;
    const int ng   = w & 3;
    const int bg   = w >> 2;
    const int n0   = blockIdx.x * 16 + ng * 4;
    const int b2s  = tid >> 4;
    const int c4   = tid & 15;

    u64 acc[8][4];
    #pragma unroll
    for (int i = 0; i < 8; i++)
        #pragma unroll
        for (int j = 0; j < 4; j++) acc[i][j] = 0ull;

    float4 lo4 = *(const float4*)(A1 + (size_t)(2 * b2s)     * K1 + c4 * 4);
    float4 hi4 = *(const float4*)(A1 + (size_t)(2 * b2s + 1) * K1 + c4 * 4);
    float w0[4], w1[4];
    #pragma unroll
    for (int j = 0; j < 4; j++) {
        const float* r = W1 + (size_t)(n0 + j) * K1 + lane;
        w0[j] = r[0]; w1[j] = r[32];
    }

    #pragma unroll 1
    for (int k0 = 0; k0 < K1; k0 += 64) {
        __syncthreads();
        xs[b2s][c4*4+0] = pack2(lo4.x, hi4.x);
        xs[b2s][c4*4+1] = pack2(lo4.y, hi4.y);
        xs[b2s][c4*4+2] = pack2(lo4.z, hi4.z);
        xs[b2s][c4*4+3] = pack2(lo4.w, hi4.w);
        __syncthreads();
        u64 wd0[4], wd1[4];
        #pragma unroll
        for (int j = 0; j < 4; j++) {
            wd0[j] = pack2(w0[j], w0[j]);
            wd1[j] = pack2(w1[j], w1[j]);
        }
        if (k0 + 64 < K1) {
            lo4 = *(const float4*)(A1 + (size_t)(2 * b2s)     * K1 + k0 + 64 + c4 * 4);
            hi4 = *(const float4*)(A1 + (size_t)(2 * b2s + 1) * K1 + k0 + 64 + c4 * 4);
            #pragma unroll
            for (int j = 0; j < 4; j++) {
                const float* r = W1 + (size_t)(n0 + j) * K1 + k0 + 64 + lane;
                w0[j] = r[0]; w1[j] = r[32];
            }
        }
        #pragma unroll
        for (int i = 0; i < 8; i++) {
            u64 x0 = xs[bg * 8 + i][lane];
            u64 x1 = xs[bg * 8 + i][lane + 32];
            #pragma unroll
            for (int j = 0; j < 4; j++) {
                acc[i][j] = ffma2(x0, wd0[j], acc[i][j]);
                acc[i][j] = ffma2(x1, wd1[j], acc[i][j]);
            }
        }
    }
    #pragma unroll
    for (int i = 0; i < 8; i++)
        #pragma unroll
        for (int j = 0; j < 4; j++) {
            u64 v = acc[i][j];
            #pragma unroll
            for (int o = 16; o > 0; o >>= 1)
                v = fadd2(v, __shfl_xor_sync(0xffffffffu, v, o));
            acc[i][j] = v;
        }
    if (lane == 0) {
        #pragma unroll
        for (int i = 0; i < 8; i++) {
            int b = (bg * 8 + i) * 2;
            #pragma unroll
            for (int j = 0; j < 4; j++) {
                int n = n0 + j;
                float lo, hi; unpack2(acc[i][j], lo, hi);
                out[(size_t)b       * ldc + n] = lo + bias1[n];
                out[(size_t)(b + 1) * ldc + n] = hi + bias1[n];
            }
        }
    }
}

// ============================================================
// Fused attention, 512 threads (R14-proven): escore (16 warps, 2 p's/iter)
// + softmax + alpha writes + embedding gather. att2 stays a skinny kernel.
// ============================================================
__global__ __launch_bounds__(512) void att_fused_kernel(
    const float* __restrict__ att1, const float* __restrict__ att2,
    const float* __restrict__ Wf,   const float* __restrict__ bf,
    float* __restrict__ alpha, float* __restrict__ out_alpha, int t,
    const int* __restrict__ captions, const float* __restrict__ emb,
    float* __restrict__ xbuf)
{
    __shared__ __align__(16) float sA[ATT];
    __shared__ __align__(16) float sW[ATT];
    __shared__ float sE[256];
    __shared__ float red[256];
    __shared__ int s_idx;

    const int b = blockIdx.x, tid = threadIdx.x;

    sA[tid] = att2[(size_t)b * ATT + tid];      // 512 threads == ATT
    sW[tid] = Wf[tid];
    if (tid < 256) sE[tid] = -3.4e38f;
    __syncthreads();

    const int w = tid >> 5, lane = tid & 31;    // 16 warps
    for (int p = w; p < PP; p += 32) {
        const int p2 = p + 16;
        const bool has2 = (p2 < PP);
        const float4* row0 = (const float4*)(att1 + ((size_t)b * PP + p) * ATT);
        const float4* row1 = (const float4*)(att1 + ((size_t)b * PP + (has2 ? p2 : p)) * ATT);
        const float4* a4  = (const float4*)sA;
        const float4* w4  = (const float4*)sW;
        float acc0 = 0.f, acc1 = 0.f;
        #pragma unroll
        for (int c = lane; c < ATT / 4; c += 32) {
            float4 h = a4[c], f = w4[c];
            float4 v0 = row0[c], v1 = row1[c];
            acc0 += fmaxf(v0.x + h.x, 0.f) * f.x + fmaxf(v0.y + h.y, 0.f) * f.y
                  + fmaxf(v0.z + h.z, 0.f) * f.z + fmaxf(v0.w + h.w, 0.f) * f.w;
            acc1 += fmaxf(v1.x + h.x, 0.f) * f.x + fmaxf(v1.y + h.y, 0.f) * f.y
                  + fmaxf(v1.z + h.z, 0.f) * f.z + fmaxf(v1.w + h.w, 0.f) * f.w;
        }
        #pragma unroll
        for (int o = 16; o > 0; o >>= 1) {
            acc0 += __shfl_xor_sync(0xffffffffu, acc0, o);
            acc1 += __shfl_xor_sync(0xffffffffu, acc1, o);
        }
        if (lane == 0) {
            sE[p] = acc0 + bf[0];
            if (has2) sE[p2] = acc1 + bf[0];
        }
    }
    __syncthreads();

    // softmax over sE[0..195] using threads 0..255
    float v = (tid < 256) ? sE[tid] : -3.4e38f;
    if (tid < 256) red[tid] = v;
    __syncthreads();
    #pragma unroll
    for (int s = 128; s > 0; s >>= 1) {
        if (tid < s) red[tid] = fmaxf(red[tid], red[tid + s]);
        __syncthreads();
    }
    float mx = red[0]; __syncthreads();
    float ex = (tid < PP) ? expf(v - mx) : 0.f;
    if (tid < 256) red[tid] = ex;
    __syncthreads();
    #pragma unroll
    for (int s = 128; s > 0; s >>= 1) {
        if (tid < s) red[tid] += red[tid + s];
        __syncthreads();
    }
    float inv = 1.0f / red[0];
    if (tid < PP) {
        float a = ex * inv;
        alpha[b * PP + tid] = a;
        out_alpha[(size_t)(b * NT + t) * PP + tid] = a;
    }

    if (tid == 0) {
        // dtype hedge: int64 captions -> every odd 32-bit word is 0
        bool is64 = true;
        #pragma unroll
        for (int i = 0; i < 32; i++)
            if (captions[2 * i + 1] != 0) is64 = false;
        int pos = b * LL + t;
        s_idx = is64 ? captions[2 * pos] : captions[pos];
    }
    __syncthreads();
    if (tid < EMB)
        xbuf[(size_t)b * XK + tid] = emb[(size_t)s_idx * EMB + tid];
}

// ============================================================
// awe: float2 per thread, p-unroll 8 (MLP 8). grid (4, NB). (R14-proven)
// ============================================================
__global__ void awe_kernel(const float* __restrict__ enc,
                           const float* __restrict__ alpha,
                           float* __restrict__ xbuf)
{
    __shared__ float al[PP];
    const int b  = blockIdx.y;
    const int k0 = blockIdx.x * 512 + threadIdx.x * 2;
    if (threadIdx.x < PP) al[threadIdx.x] = alpha[b * PP + threadIdx.x];
    __syncthreads();
    const float2* ep = (const float2*)(enc + (size_t)b * PP * ENC) + (k0 >> 1);
    float ax = 0.f, ay = 0.f;
    #pragma unroll 8
    for (int p = 0; p < PP; p++) {
        float a = al[p];
        float2 v = ep[(size_t)p * (ENC / 2)];
        ax += a * v.x; ay += a * v.y;
    }
    xbuf[(size_t)b * XK + EMB + k0]     = ax;
    xbuf[(size_t)b * XK + EMB + k0 + 1] = ay;
}

// ============================================================
// Gates GEMM + fused LSTM, double-buffered staging (ONE sync per chunk),
// pipelined across Wih/Whh.
// ============================================================
#define NCH (XK / 64 + DECD / 64)   // 44 chunks
__global__ __launch_bounds__(256) void gates_lstm_kernel(
    const float* __restrict__ x,    const float* __restrict__ Wih,
    const float* __restrict__ h_in, const float* __restrict__ Whh,
    const float* __restrict__ bih,  const float* __restrict__ bhh,
    float* __restrict__ c, float* __restrict__ h_out)
{
    __shared__ __align__(16) u64 xs[2][16][64];
    const int tid  = threadIdx.x;
    const int lane = tid & 31;
    const int wrp  = tid >> 5;
    const int ng   = wrp & 3;
    const int bg   = wrp >> 2;
    const int jcol = blockIdx.x * 4 + ng;
    const int b2s  = tid >> 4;
    const int c4   = tid & 15;

    int nj[4];
    #pragma unroll
    for (int j = 0; j < 4; j++) nj[j] = j * DECD + jcol;

    u64 acc[8][4];
    #pragma unroll
    for (int i = 0; i < 8; i++)
        #pragma unroll
        for (int j = 0; j < 4; j++) acc[i][j] = 0ull;

    float4 lo4 = *(const float4*)(x + (size_t)(2 * b2s)     * XK + c4 * 4);
    float4 hi4 = *(const float4*)(x + (size_t)(2 * b2s + 1) * XK + c4 * 4);
    float w0[4], w1[4];
    #pragma unroll
    for (int j = 0; j < 4; j++) {
        const float* r = Wih + (size_t)nj[j] * XK + lane;
        w0[j] = r[0]; w1[j] = r[32];
    }

    #pragma unroll 1
    for (int cc = 0; cc < NCH; cc++) {
        const int buf = cc & 1;
        // stage current chunk (writers touch buf, prior readers used buf^1)
        xs[buf][b2s][c4*4+0] = pack2(lo4.x, hi4.x);
        xs[buf][b2s][c4*4+1] = pack2(lo4.y, hi4.y);
        xs[buf][b2s][c4*4+2] = pack2(lo4.z, hi4.z);
        xs[buf][b2s][c4*4+3] = pack2(lo4.w, hi4.w);
        __syncthreads();
        u64 wd0[4], wd1[4];
        #pragma unroll
        for (int j = 0; j < 4; j++) {
            wd0[j] = pack2(w0[j], w0[j]);
            wd1[j] = pack2(w1[j], w1[j]);
        }
        if (cc + 1 < NCH) {   // prefetch next chunk (maybe next segment)
            int nc = cc + 1;
            const float* An; const float* Wn; int Kn, kn;
            if (nc < XK / 64) { An = x;    Wn = Wih; Kn = XK;   kn = nc * 64; }
            else              { An = h_in; Wn = Whh; Kn = DECD; kn = (nc - XK / 64) * 64; }
            lo4 = *(const float4*)(An + (size_t)(2 * b2s)     * Kn + kn + c4 * 4);
            hi4 = *(const float4*)(An + (size_t)(2 * b2s + 1) * Kn + kn + c4 * 4);
            #pragma unroll
            for (int j = 0; j < 4; j++) {
                const float* r = Wn + (size_t)nj[j] * Kn + kn + lane;
                w0[j] = r[0]; w1[j] = r[32];
            }
        }
        #pragma unroll
        for (int i = 0; i < 8; i++) {
            u64 x0 = xs[buf][bg * 8 + i][lane];
            u64 x1 = xs[buf][bg * 8 + i][lane + 32];
            #pragma unroll
            for (int j = 0; j < 4; j++) {
                acc[i][j] = ffma2(x0, wd0[j], acc[i][j]);
                acc[i][j] = ffma2(x1, wd1[j], acc[i][j]);
            }
        }
    }
    #pragma unroll
    for (int i = 0; i < 8; i++)
        #pragma unroll
        for (int j = 0; j < 4; j++) {
            u64 v = acc[i][j];
            #pragma unroll
            for (int o = 16; o > 0; o >>= 1)
                v = fadd2(v, __shfl_xor_sync(0xffffffffu, v, o));
            acc[i][j] = v;
        }
    if (lane == 0) {
        #pragma unroll
        for (int i = 0; i < 8; i++) {
            int b0 = (bg * 8 + i) * 2;
            float gv[4][2];
            #pragma unroll
            for (int j = 0; j < 4; j++) {
                float bb = bih[nj[j]] + bhh[nj[j]];
                float lo, hi; unpack2(acc[i][j], lo, hi);
                gv[j][0] = lo + bb; gv[j][1] = hi + bb;
            }
            #pragma unroll
            for (int hs = 0; hs < 2; hs++) {
                int bb = b0 + hs;
                float ig = gv[0][hs], fg = gv[1][hs];
                float gg = gv[2][hs], og = gv[3][hs];
                float si = 1.f / (1.f + expf(-ig));
                float sf = 1.f / (1.f + expf(-fg));
                float so = 1.f / (1.f + expf(-og));
                float co = c[(size_t)bb * DECD + jcol];
                float cn = sf * co + si * tanhf(gg);
                float hn = so * tanhf(cn);
                c[(size_t)bb * DECD + jcol]     = cn;
                h_out[(size_t)bb * DECD + jcol] = hn;
            }
        }
    }
}

// ============================================================
extern "C" void kernel_launch(void* const* d_in, const int* in_sizes, int n_in,
                              void* d_out, int out_size)
{
    const float* enc  = (const float*)d_in[0];
    const int*   caps = (const int*)  d_in[1];
    const float* emb  = (const float*)d_in[3];
    const float* We   = (const float*)d_in[4];
    const float* be   = (const float*)d_in[5];
    const float* Wd   = (const float*)d_in[6];
    const float* bd   = (const float*)d_in[7];
    const float* Wf   = (const float*)d_in[8];
    const float* bf   = (const float*)d_in[9];
    const float* Wih  = (const float*)d_in[10];
    const float* bih  = (const float*)d_in[11];
    const float* Whh  = (const float*)d_in[12];
    const float* bhh  = (const float*)d_in[13];
    const float* Wfc  = (const float*)d_in[14];
    const float* bfc  = (const float*)d_in[15];
    const float* Wh0  = (const float*)d_in[16];
    const float* bh0  = (const float*)d_in[17];
    const float* Wc0  = (const float*)d_in[18];
    const float* bc0  = (const float*)d_in[19];

    float* out       = (float*)d_out;                  // predictions [32,20,30000]
    float* out_alpha = out + (size_t)NB * NT * NV;     // alphas      [32,20,196]

    float *p_att1, *p_mean, *p_h, *p_c, *p_att2, *p_alpha, *p_x, *p_hall;
    cudaGetSymbolAddress((void**)&p_att1,  g_att1);
    cudaGetSymbolAddress((void**)&p_mean,  g_mean);
    cudaGetSymbolAddress((void**)&p_h,     g_h);
    cudaGetSymbolAddress((void**)&p_c,     g_c);
    cudaGetSymbolAddress((void**)&p_att2,  g_att2);
    cudaGetSymbolAddress((void**)&p_alpha, g_alpha);
    cudaGetSymbolAddress((void**)&p_x,     g_x);
    cudaGetSymbolAddress((void**)&p_hall,  g_hall);

    const int dyn_smem = 3 * 2 * SBUF * 4;   // 110,592 bytes
    cudaFuncSetAttribute(gemm_tc3_kernel,
                         cudaFuncAttributeMaxDynamicSharedMemorySize, dyn_smem);

    // ---- init ----
    mean_kernel<<<NB, 256>>>(enc, p_mean);
    skinny_pipe_kernel<<<DECD / 16, 256>>>(p_mean, Wh0, ENC, bh0, p_h, DECD);
    skinny_pipe_kernel<<<DECD / 16, 256>>>(p_mean, Wc0, ENC, bc0, p_c, DECD);
    gemm_tc3_kernel<<<dim3(ATT / 128, (NB * PP) / 128), 256, dyn_smem>>>(
        enc, We, be, p_att1, ENC, ATT, ATT, 0);

    // ---- decode loop: 4 launches/step (R14-proven structure) ----
    for (int t = 0; t < NT; t++) {
        const float* h_in  = (t == 0) ? p_h : (p_hall + (size_t)(t - 1) * NB * DECD);
        float*       h_out = p_hall + (size_t)t * NB * DECD;
        skinny_pipe_kernel<<<ATT / 16, 256>>>(h_in, Wd, DECD, bd, p_att2, ATT);
        att_fused_kernel<<<NB, 512>>>(p_att1, p_att2, Wf, bf, p_alpha,
                                      out_alpha, t, caps, emb, p_x);
        awe_kernel<<<dim3(4, NB), 256>>>(enc, p_alpha, p_x);
        gates_lstm_kernel<<<DECD / 4, 256>>>(p_x, Wih, h_in, Whh,
                                             bih, bhh, p_c, h_out);
    }

    // ---- batched predictions: [640,512] @ [512,30000]^T, rows remapped ----
    gemm_tc3_kernel<<<dim3((NV + 127) / 128, (NT * NB) / 128), 256, dyn_smem>>>(
        p_hall, Wfc, bfc, out, DECD, NV, 0, 1);
}

// round 17
// speedup vs baseline: 1.3132x; 1.0198x over previous
#include <cuda_runtime.h>
#include <math.h>

#define NB   32      // batch
#define PP   196     // pixels
#define ENC  2048
#define DECD 512
#define ATT  512
#define EMB  256
#define NV   30000
#define LL   21
#define NT   20      // decode steps
#define XK   (EMB + ENC)   // 2304

typedef unsigned long long u64;

// ---------- packed f32x2 helpers (sm_103a) ----------
__device__ __forceinline__ u64 pack2(float lo, float hi) {
    u64 r; asm("mov.b64 %0, {%1, %2};" : "=l"(r) : "f"(lo), "f"(hi)); return r;
}
__device__ __forceinline__ void unpack2(u64 v, float& lo, float& hi) {
    asm("mov.b64 {%0, %1}, %2;" : "=f"(lo), "=f"(hi) : "l"(v));
}
__device__ __forceinline__ u64 ffma2(u64 a, u64 b, u64 c) {
    u64 d; asm("fma.rn.f32x2 %0, %1, %2, %3;" : "=l"(d) : "l"(a), "l"(b), "l"(c)); return d;
}
__device__ __forceinline__ u64 fadd2(u64 a, u64 b) {
    u64 d; asm("add.rn.f32x2 %0, %1, %2;" : "=l"(d) : "l"(a), "l"(b)); return d;
}
__device__ __forceinline__ unsigned to_tf32(float f) {
    unsigned r; asm("cvt.rna.tf32.f32 %0, %1;" : "=r"(r) : "f"(f)); return r;
}

// ---------- cluster / DSMEM helpers ----------
__device__ __forceinline__ unsigned smem_u32(const void* p) {
    unsigned r;
    asm("{ .reg .u64 t; cvta.to.shared.u64 t, %1; cvt.u32.u64 %0, t; }"
        : "=r"(r) : "l"(p));
    return r;
}
__device__ __forceinline__ unsigned mapa_rank0(unsigned a) {
    unsigned r, z = 0;
    asm("mapa.shared::cluster.u32 %0, %1, %2;" : "=r"(r) : "r"(a), "r"(z));
    return r;
}
__device__ __forceinline__ void st_cl_f32(unsigned a, float v) {
    asm volatile("st.shared::cluster.f32 [%0], %1;" :: "r"(a), "f"(v) : "memory");
}
__device__ __forceinline__ float ld_cl_f32(unsigned a) {
    float v; asm volatile("ld.shared::cluster.f32 %0, [%1];" : "=f"(v) : "r"(a) : "memory");
    return v;
}
#define CLUSTER_SYNC() do { \
    asm volatile("barrier.cluster.arrive.aligned;" ::: "memory"); \
    asm volatile("barrier.cluster.wait.aligned;"   ::: "memory"); } while (0)

// ---------- persistent scratch (no cudaMalloc allowed) ----------
__device__ __align__(16) float g_att1 [NB * PP * ATT];     // 12.8 MB
__device__ __align__(16) float g_mean [NB * ENC];
__device__ __align__(16) float g_h    [NB * DECD];         // h0
__device__ __align__(16) float g_c    [NB * DECD];
__device__ __align__(16) float g_x    [NB * XK];
__device__ __align__(16) float g_hall [NT * NB * DECD];    // h_t, rows m = t*32+b

// ============================================================
// mean over P
// ============================================================
__global__ void mean_kernel(const float* __restrict__ enc, float* __restrict__ mean)
{
    int b = blockIdx.x;
    for (int k = threadIdx.x; k < ENC; k += 256) {
        const float* p0 = enc + (size_t)b * PP * ENC + k;
        float s = 0.f;
        #pragma unroll 4
        for (int p = 0; p < PP; p++) s += p0[(size_t)p * ENC];
        mean[b * ENC + k] = s * (1.0f / PP);
    }
}

// ============================================================
// TC GEMM v3 + cvt.rna restored: 128x128 tile, BK=32, 3-stage cp.async,
// ONE __syncthreads per k-tile, tf32 m16n8k8.
// Dynamic smem: 3 * 2 * 128*36 * 4 = 110,592 bytes.
// ============================================================
#define TLE  36
#define SBUF (128 * TLE)

__global__ __launch_bounds__(256) void gemm_tc3_kernel(
    const float* __restrict__ A, const float* __restrict__ W,
    const float* __restrict__ bias, float* __restrict__ C,
    int K, int Ntot, int ldc, int remap)
{
    extern __shared__ __align__(16) unsigned smem_dyn[];
    unsigned sbase;
    asm("{ .reg .u64 t; cvta.to.shared.u64 t, %1; cvt.u32.u64 %0, t; }"
        : "=r"(sbase) : "l"(smem_dyn));

    const int tid  = threadIdx.x;
    const int m0   = blockIdx.y * 128;
    const int n0   = blockIdx.x * 128;
    const int lane = tid & 31;
    const int warp = tid >> 5;
    const int wm   = warp >> 2;
    const int wn   = warp & 3;
    const int g    = lane >> 2;
    const int tig  = lane & 3;

    float acc[4][4][4];
    #pragma unroll
    for (int i = 0; i < 4; i++)
        #pragma unroll
        for (int j = 0; j < 4; j++)
            #pragma unroll
            for (int q = 0; q < 4; q++) acc[i][j][q] = 0.f;

    const int KT = K >> 5;

    int srow[4], scol[4];
    #pragma unroll
    for (int r = 0; r < 4; r++) {
        int f = tid + r * 256;
        srow[r] = f >> 3;
        scol[r] = f & 7;
    }

    auto issue = [&](int kt) {
        const int s = kt % 3;
        const int kbase = kt * 32;
        const unsigned aB = sbase + (unsigned)(s * 2 * SBUF * 4);
        const unsigned bB = aB + (unsigned)(SBUF * 4);
        #pragma unroll
        for (int r = 0; r < 4; r++) {
            const float* src = A + (size_t)(m0 + srow[r]) * K + kbase + scol[r] * 4;
            unsigned dst = aB + (unsigned)((srow[r] * TLE + scol[r] * 4) * 4);
            asm volatile("cp.async.cg.shared.global [%0], [%1], 16;"
                         :: "r"(dst), "l"(src));
        }
        #pragma unroll
        for (int r = 0; r < 4; r++) {
            int n = n0 + srow[r];
            if (n >= Ntot) n = Ntot - 1;
            const float* src = W + (size_t)n * K + kbase + scol[r] * 4;
            unsigned dst = bB + (unsigned)((srow[r] * TLE + scol[r] * 4) * 4);
            asm volatile("cp.async.cg.shared.global [%0], [%1], 16;"
                         :: "r"(dst), "l"(src));
        }
        asm volatile("cp.async.commit_group;");
    };

    issue(0);
    issue(1);

    #pragma unroll 1
    for (int kt = 0; kt < KT; kt++) {
        asm volatile("cp.async.wait_group 1;");
        __syncthreads();
        if (kt + 2 < KT) issue(kt + 2);
        else asm volatile("cp.async.commit_group;");

        const unsigned* as = smem_dyn + (kt % 3) * 2 * SBUF;
        const unsigned* bs = as + SBUF;

        #pragma unroll
        for (int kc = 0; kc < 4; kc++) {
            const int kb = kc * 8;
            unsigned bF[4][2];
            #pragma unroll
            for (int j = 0; j < 4; j++) {
                int nl = wn * 32 + j * 8 + g;
                bF[j][0] = to_tf32(__uint_as_float(bs[nl * TLE + kb + tig]));
                bF[j][1] = to_tf32(__uint_as_float(bs[nl * TLE + kb + tig + 4]));
            }
            #pragma unroll
            for (int i = 0; i < 4; i++) {
                int ml = wm * 64 + i * 16 + g;
                unsigned a0 = to_tf32(__uint_as_float(as[ml * TLE + kb + tig]));
                unsigned a1 = to_tf32(__uint_as_float(as[(ml + 8) * TLE + kb + tig]));
                unsigned a2 = to_tf32(__uint_as_float(as[ml * TLE + kb + tig + 4]));
                unsigned a3 = to_tf32(__uint_as_float(as[(ml + 8) * TLE + kb + tig + 4]));
                #pragma unroll
                for (int j = 0; j < 4; j++) {
                    asm volatile(
                        "mma.sync.aligned.m16n8k8.row.col.f32.tf32.tf32.f32 "
                        "{%0,%1,%2,%3}, {%4,%5,%6,%7}, {%8,%9}, {%0,%1,%2,%3};"
                        : "+f"(acc[i][j][0]), "+f"(acc[i][j][1]),
                          "+f"(acc[i][j][2]), "+f"(acc[i][j][3])
                        : "r"(a0), "r"(a1), "r"(a2), "r"(a3),
                          "r"(bF[j][0]), "r"(bF[j][1]));
                }
            }
        }
    }

    #pragma unroll
    for (int i = 0; i < 4; i++) {
        int r0 = m0 + wm * 64 + i * 16 + g;
        #pragma unroll
        for (int j = 0; j < 4; j++) {
            int nb = n0 + wn * 32 + j * 8 + tig * 2;
            #pragma unroll
            for (int q = 0; q < 4; q++) {
                int m = r0 + (q >> 1) * 8;
                int n = nb + (q & 1);
                if (n >= Ntot) continue;
                float v = acc[i][j][q] + bias[n];
                if (remap) {
                    int tt = m >> 5, bb = m & 31;
                    C[(size_t)(bb * NT + tt) * Ntot + n] = v;
                } else {
                    C[(size_t)m * ldc + n] = v;
                }
            }
        }
    }
}

// ============================================================
// Pipelined skinny GEMM (init h0/c0 only; R9/R10-proven)
// ============================================================
__global__ __launch_bounds__(256) void skinny_pipe_kernel(
    const float* __restrict__ A1, const float* __restrict__ W1, int K1,
    const float* __restrict__ bias1, float* __restrict__ out, int ldc)
{
    __shared__ __align__(16) u64 xs[16][64];
    const int tid  = threadIdx.x;
    const int lane = tid & 31;
    const int w    = tid >> 5;
    const int ng   = w & 3;
    const int bg   = w >> 2;
    const int n0   = blockIdx.x * 16 + ng * 4;
    const int b2s  = tid >> 4;
    const int c4   = tid & 15;

    u64 acc[8][4];
    #pragma unroll
    for (int i = 0; i < 8; i++)
        #pragma unroll
        for (int j = 0; j < 4; j++) acc[i][j] = 0ull;

    float4 lo4 = *(const float4*)(A1 + (size_t)(2 * b2s)     * K1 + c4 * 4);
    float4 hi4 = *(const float4*)(A1 + (size_t)(2 * b2s + 1) * K1 + c4 * 4);
    float w0[4], w1[4];
    #pragma unroll
    for (int j = 0; j < 4; j++) {
        const float* r = W1 + (size_t)(n0 + j) * K1 + lane;
        w0[j] = r[0]; w1[j] = r[32];
    }

    #pragma unroll 1
    for (int k0 = 0; k0 < K1; k0 += 64) {
        __syncthreads();
        xs[b2s][c4*4+0] = pack2(lo4.x, hi4.x);
        xs[b2s][c4*4+1] = pack2(lo4.y, hi4.y);
        xs[b2s][c4*4+2] = pack2(lo4.z, hi4.z);
        xs[b2s][c4*4+3] = pack2(lo4.w, hi4.w);
        __syncthreads();
        u64 wd0[4], wd1[4];
        #pragma unroll
        for (int j = 0; j < 4; j++) {
            wd0[j] = pack2(w0[j], w0[j]);
            wd1[j] = pack2(w1[j], w1[j]);
        }
        if (k0 + 64 < K1) {
            lo4 = *(const float4*)(A1 + (size_t)(2 * b2s)     * K1 + k0 + 64 + c4 * 4);
            hi4 = *(const float4*)(A1 + (size_t)(2 * b2s + 1) * K1 + k0 + 64 + c4 * 4);
            #pragma unroll
            for (int j = 0; j < 4; j++) {
                const float* r = W1 + (size_t)(n0 + j) * K1 + k0 + 64 + lane;
                w0[j] = r[0]; w1[j] = r[32];
            }
        }
        #pragma unroll
        for (int i = 0; i < 8; i++) {
            u64 x0 = xs[bg * 8 + i][lane];
            u64 x1 = xs[bg * 8 + i][lane + 32];
            #pragma unroll
            for (int j = 0; j < 4; j++) {
                acc[i][j] = ffma2(x0, wd0[j], acc[i][j]);
                acc[i][j] = ffma2(x1, wd1[j], acc[i][j]);
            }
        }
    }
    #pragma unroll
    for (int i = 0; i < 8; i++)
        #pragma unroll
        for (int j = 0; j < 4; j++) {
            u64 v = acc[i][j];
            #pragma unroll
            for (int o = 16; o > 0; o >>= 1)
                v = fadd2(v, __shfl_xor_sync(0xffffffffu, v, o));
            acc[i][j] = v;
        }
    if (lane == 0) {
        #pragma unroll
        for (int i = 0; i < 8; i++) {
            int b = (bg * 8 + i) * 2;
            #pragma unroll
            for (int j = 0; j < 4; j++) {
                int n = n0 + j;
                float lo, hi; unpack2(acc[i][j], lo, hi);
                out[(size_t)b       * ldc + n] = lo + bias1[n];
                out[(size_t)(b + 1) * ldc + n] = hi + bias1[n];
            }
        }
    }
}

// ============================================================
// CLUSTER attention kernel: 4 CTAs per batch element (cluster (4,1,1)).
// Phase 1: att2 (each rank computes 128 Wd rows -> rank0 sA via DSMEM)
// Phase 2: escore (32 warps across cluster -> rank0 sE)
// Phase 3: softmax + alpha out + emb gather (rank0)
// Phase 4: awe (each rank does 512 k's) -> g_x
// Replaces 3 kernels (att2 skinny, att_fused, awe) with one node.
// ============================================================
__global__ __launch_bounds__(256) __cluster_dims__(4, 1, 1)
void cluster_att_kernel(
    const float* __restrict__ att1, const float* __restrict__ h_in,
    const float* __restrict__ Wd,   const float* __restrict__ bd,
    const float* __restrict__ Wf,   const float* __restrict__ bf,
    float* __restrict__ out_alpha, int t,
    const int* __restrict__ captions, const float* __restrict__ emb,
    const float* __restrict__ enc, float* __restrict__ xbuf)
{
    __shared__ __align__(16) float sH[DECD];
    __shared__ __align__(16) float sA[ATT];
    __shared__ __align__(16) float sW[ATT];
    __shared__ float sE[256];
    __shared__ float red[256];
    __shared__ float sAl[PP];
    __shared__ int   s_idx;

    const int tid = threadIdx.x;
    unsigned rank; asm("mov.u32 %0, %%cluster_ctarank;" : "=r"(rank));
    const int b = blockIdx.x >> 2;

    sH[tid]       = h_in[(size_t)b * DECD + tid];
    sH[tid + 256] = h_in[(size_t)b * DECD + tid + 256];
    sW[tid]       = Wf[tid];
    sW[tid + 256] = Wf[tid + 256];
    if (rank == 0) sE[tid] = -3.4e38f;
    __syncthreads();

    // ---- Phase 1: att2 rows [rank*128, rank*128+128) ----
    {
        const int rl = tid & 127, half = tid >> 7;
        const int row = (int)rank * 128 + rl;
        const float4* wr = (const float4*)(Wd + (size_t)row * DECD + half * 256);
        const float4* hh = (const float4*)(sH + half * 256);
        float acc = 0.f;
        #pragma unroll 8
        for (int kk = 0; kk < 64; kk++) {
            float4 w4 = wr[kk], h4 = hh[kk];
            acc += w4.x * h4.x + w4.y * h4.y + w4.z * h4.z + w4.w * h4.w;
        }
        red[tid] = acc;
        __syncthreads();
        if (tid < 128) {
            int row0 = (int)rank * 128 + tid;
            float v = red[tid] + red[tid + 128] + bd[row0];
            st_cl_f32(mapa_rank0(smem_u32(&sA[row0])), v);
        }
    }
    CLUSTER_SYNC();   // att2 complete in rank0's sA

    // copy sA from rank0 to local (rank0 already has it)
    if (rank != 0) {
        sA[tid]       = ld_cl_f32(mapa_rank0(smem_u32(&sA[tid])));
        sA[tid + 256] = ld_cl_f32(mapa_rank0(smem_u32(&sA[tid + 256])));
    }
    __syncthreads();

    // ---- Phase 2: escore, 32 warps across the cluster ----
    {
        const int warp = tid >> 5, lane = tid & 31;
        const int gw = (int)rank * 8 + warp;
        for (int p = gw; p < PP; p += 32) {
            const float4* row = (const float4*)(att1 + ((size_t)b * PP + p) * ATT);
            const float4* a4  = (const float4*)sA;
            const float4* w4  = (const float4*)sW;
            float acc = 0.f;
            #pragma unroll
            for (int c = lane; c < ATT / 4; c += 32) {
                float4 v = row[c], h = a4[c], f = w4[c];
                acc += fmaxf(v.x + h.x, 0.f) * f.x + fmaxf(v.y + h.y, 0.f) * f.y
                     + fmaxf(v.z + h.z, 0.f) * f.z + fmaxf(v.w + h.w, 0.f) * f.w;
            }
            #pragma unroll
            for (int o = 16; o > 0; o >>= 1)
                acc += __shfl_xor_sync(0xffffffffu, acc, o);
            if (lane == 0)
                st_cl_f32(mapa_rank0(smem_u32(&sE[p])), acc + bf[0]);
        }
    }
    CLUSTER_SYNC();   // escore complete in rank0's sE

    // ---- Phase 3: softmax + alpha out + emb gather (rank0 only) ----
    if (rank == 0) {
        float v = sE[tid];
        red[tid] = v; __syncthreads();
        #pragma unroll
        for (int s = 128; s > 0; s >>= 1) {
            if (tid < s) red[tid] = fmaxf(red[tid], red[tid + s]);
            __syncthreads();
        }
        float mx = red[0]; __syncthreads();
        float ex = (tid < PP) ? expf(v - mx) : 0.f;
        red[tid] = ex; __syncthreads();
        #pragma unroll
        for (int s = 128; s > 0; s >>= 1) {
            if (tid < s) red[tid] += red[tid + s];
            __syncthreads();
        }
        float inv = 1.0f / red[0];
        if (tid < PP) {
            float a = ex * inv;
            sAl[tid] = a;
            out_alpha[(size_t)(b * NT + t) * PP + tid] = a;
        }
        if (tid == 0) {
            // dtype hedge: int64 captions -> every odd 32-bit word is 0
            bool is64 = true;
            #pragma unroll
            for (int i = 0; i < 32; i++)
                if (captions[2 * i + 1] != 0) is64 = false;
            int pos = b * LL + t;
            s_idx = is64 ? captions[2 * pos] : captions[pos];
        }
        __syncthreads();
        xbuf[(size_t)b * XK + tid] = emb[(size_t)s_idx * EMB + tid];  // 256 == EMB
    }
    CLUSTER_SYNC();   // alpha ready in rank0's sAl

    // ---- Phase 4: awe slice (512 k's per rank) ----
    if (rank != 0 && tid < PP)
        sAl[tid] = ld_cl_f32(mapa_rank0(smem_u32(&sAl[tid])));
    __syncthreads();
    {
        const int k0 = (int)rank * 512 + tid * 2;
        const float2* ep = (const float2*)(enc + (size_t)b * PP * ENC) + (k0 >> 1);
        float ax = 0.f, ay = 0.f;
        #pragma unroll 8
        for (int p = 0; p < PP; p++) {
            float a = sAl[p];
            float2 v = ep[(size_t)p * (ENC / 2)];
            ax += a * v.x; ay += a * v.y;
        }
        xbuf[(size_t)b * XK + EMB + k0]     = ax;
        xbuf[(size_t)b * XK + EMB + k0 + 1] = ay;
    }
}

// ============================================================
// Gates GEMM + fused LSTM (R16-proven), double-buffered staging,
// pipelined across Wih/Whh.
// ============================================================
#define NCH (XK / 64 + DECD / 64)   // 44 chunks
__global__ __launch_bounds__(256) void gates_lstm_kernel(
    const float* __restrict__ x,    const float* __restrict__ Wih,
    const float* __restrict__ h_in, const float* __restrict__ Whh,
    const float* __restrict__ bih,  const float* __restrict__ bhh,
    float* __restrict__ c, float* __restrict__ h_out)
{
    __shared__ __align__(16) u64 xs[2][16][64];
    const int tid  = threadIdx.x;
    const int lane = tid & 31;
    const int wrp  = tid >> 5;
    const int ng   = wrp & 3;
    const int bg   = wrp >> 2;
    const int jcol = blockIdx.x * 4 + ng;
    const int b2s  = tid >> 4;
    const int c4   = tid & 15;

    int nj[4];
    #pragma unroll
    for (int j = 0; j < 4; j++) nj[j] = j * DECD + jcol;

    u64 acc[8][4];
    #pragma unroll
    for (int i = 0; i < 8; i++)
        #pragma unroll
        for (int j = 0; j < 4; j++) acc[i][j] = 0ull;

    float4 lo4 = *(const float4*)(x + (size_t)(2 * b2s)     * XK + c4 * 4);
    float4 hi4 = *(const float4*)(x + (size_t)(2 * b2s + 1) * XK + c4 * 4);
    float w0[4], w1[4];
    #pragma unroll
    for (int j = 0; j < 4; j++) {
        const float* r = Wih + (size_t)nj[j] * XK + lane;
        w0[j] = r[0]; w1[j] = r[32];
    }

    #pragma unroll 1
    for (int cc = 0; cc < NCH; cc++) {
        const int buf = cc & 1;
        xs[buf][b2s][c4*4+0] = pack2(lo4.x, hi4.x);
        xs[buf][b2s][c4*4+1] = pack2(lo4.y, hi4.y);
        xs[buf][b2s][c4*4+2] = pack2(lo4.z, hi4.z);
        xs[buf][b2s][c4*4+3] = pack2(lo4.w, hi4.w);
        __syncthreads();
        u64 wd0[4], wd1[4];
        #pragma unroll
        for (int j = 0; j < 4; j++) {
            wd0[j] = pack2(w0[j], w0[j]);
            wd1[j] = pack2(w1[j], w1[j]);
        }
        if (cc + 1 < NCH) {
            int nc = cc + 1;
            const float* An; const float* Wn; int Kn, kn;
            if (nc < XK / 64) { An = x;    Wn = Wih; Kn = XK;   kn = nc * 64; }
            else              { An = h_in; Wn = Whh; Kn = DECD; kn = (nc - XK / 64) * 64; }
            lo4 = *(const float4*)(An + (size_t)(2 * b2s)     * Kn + kn + c4 * 4);
            hi4 = *(const float4*)(An + (size_t)(2 * b2s + 1) * Kn + kn + c4 * 4);
            #pragma unroll
            for (int j = 0; j < 4; j++) {
                const float* r = Wn + (size_t)nj[j] * Kn + kn + lane;
                w0[j] = r[0]; w1[j] = r[32];
            }
        }
        #pragma unroll
        for (int i = 0; i < 8; i++) {
            u64 x0 = xs[buf][bg * 8 + i][lane];
            u64 x1 = xs[buf][bg * 8 + i][lane + 32];
            #pragma unroll
            for (int j = 0; j < 4; j++) {
                acc[i][j] = ffma2(x0, wd0[j], acc[i][j]);
                acc[i][j] = ffma2(x1, wd1[j], acc[i][j]);
            }
        }
    }
    #pragma unroll
    for (int i = 0; i < 8; i++)
        #pragma unroll
        for (int j = 0; j < 4; j++) {
            u64 v = acc[i][j];
            #pragma unroll
            for (int o = 16; o > 0; o >>= 1)
                v = fadd2(v, __shfl_xor_sync(0xffffffffu, v, o));
            acc[i][j] = v;
        }
    if (lane == 0) {
        #pragma unroll
        for (int i = 0; i < 8; i++) {
            int b0 = (bg * 8 + i) * 2;
            float gv[4][2];
            #pragma unroll
            for (int j = 0; j < 4; j++) {
                float bb = bih[nj[j]] + bhh[nj[j]];
                float lo, hi; unpack2(acc[i][j], lo, hi);
                gv[j][0] = lo + bb; gv[j][1] = hi + bb;
            }
            #pragma unroll
            for (int hs = 0; hs < 2; hs++) {
                int bb = b0 + hs;
                float ig = gv[0][hs], fg = gv[1][hs];
                float gg = gv[2][hs], og = gv[3][hs];
                float si = 1.f / (1.f + expf(-ig));
                float sf = 1.f / (1.f + expf(-fg));
                float so = 1.f / (1.f + expf(-og));
                float co = c[(size_t)bb * DECD + jcol];
                float cn = sf * co + si * tanhf(gg);
                float hn = so * tanhf(cn);
                c[(size_t)bb * DECD + jcol]     = cn;
                h_out[(size_t)bb * DECD + jcol] = hn;
            }
        }
    }
}

// ============================================================
extern "C" void kernel_launch(void* const* d_in, const int* in_sizes, int n_in,
                              void* d_out, int out_size)
{
    const float* enc  = (const float*)d_in[0];
    const int*   caps = (const int*)  d_in[1];
    const float* emb  = (const float*)d_in[3];
    const float* We   = (const float*)d_in[4];
    const float* be   = (const float*)d_in[5];
    const float* Wd   = (const float*)d_in[6];
    const float* bd   = (const float*)d_in[7];
    const float* Wf   = (const float*)d_in[8];
    const float* bf   = (const float*)d_in[9];
    const float* Wih  = (const float*)d_in[10];
    const float* bih  = (const float*)d_in[11];
    const float* Whh  = (const float*)d_in[12];
    const float* bhh  = (const float*)d_in[13];
    const float* Wfc  = (const float*)d_in[14];
    const float* bfc  = (const float*)d_in[15];
    const float* Wh0  = (const float*)d_in[16];
    const float* bh0  = (const float*)d_in[17];
    const float* Wc0  = (const float*)d_in[18];
    const float* bc0  = (const float*)d_in[19];

    float* out       = (float*)d_out;                  // predictions [32,20,30000]
    float* out_alpha = out + (size_t)NB * NT * NV;     // alphas      [32,20,196]

    float *p_att1, *p_mean, *p_h, *p_c, *p_x, *p_hall;
    cudaGetSymbolAddress((void**)&p_att1, g_att1);
    cudaGetSymbolAddress((void**)&p_mean, g_mean);
    cudaGetSymbolAddress((void**)&p_h,    g_h);
    cudaGetSymbolAddress((void**)&p_c,    g_c);
    cudaGetSymbolAddress((void**)&p_x,    g_x);
    cudaGetSymbolAddress((void**)&p_hall, g_hall);

    const int dyn_smem = 3 * 2 * SBUF * 4;   // 110,592 bytes
    cudaFuncSetAttribute(gemm_tc3_kernel,
                         cudaFuncAttributeMaxDynamicSharedMemorySize, dyn_smem);

    // ---- init ----
    mean_kernel<<<NB, 256>>>(enc, p_mean);
    skinny_pipe_kernel<<<DECD / 16, 256>>>(p_mean, Wh0, ENC, bh0, p_h, DECD);
    skinny_pipe_kernel<<<DECD / 16, 256>>>(p_mean, Wc0, ENC, bc0, p_c, DECD);
    gemm_tc3_kernel<<<dim3(ATT / 128, (NB * PP) / 128), 256, dyn_smem>>>(
        enc, We, be, p_att1, ENC, ATT, ATT, 0);

    // ---- decode loop: 2 launches/step ----
    for (int t = 0; t < NT; t++) {
        const float* h_in  = (t == 0) ? p_h : (p_hall + (size_t)(t - 1) * NB * DECD);
        float*       h_out = p_hall + (size_t)t * NB * DECD;
        cluster_att_kernel<<<4 * NB, 256>>>(p_att1, h_in, Wd, bd, Wf, bf,
                                            out_alpha, t, caps, emb, enc, p_x);
        gates_lstm_kernel<<<DECD / 4, 256>>>(p_x, Wih, h_in, Whh,
                                             bih, bhh, p_c, h_out);
    }

    // ---- batched predictions: [640,512] @ [512,30000]^T, rows remapped ----
    gemm_tc3_kernel<<<dim3((NV + 127) / 128, (NT * NB) / 128), 256, dyn_smem>>>(
        p_hall, Wfc, bfc, out, DECD, NV, 0, 1);
}